// round 1
// baseline (speedup 1.0000x reference)
#include <cuda_runtime.h>
#include <cstdint>

// Problem constants (B=2, S=4096, D=2048, E=8, DFF=8192, TOP_K=2)
#define NTOK   8192
#define DMODEL 2048
#define NEXP   8
#define FFDIM  8192
#define TOPK   2

// ---------------- device scratch (allocation-free rule: __device__ globals) --
__device__ float g_logits[NTOK * NEXP];
__device__ float g_sums[NEXP];
__device__ int   g_sel[TOPK];
__device__ float g_rw[NTOK * TOPK];
__device__ float g_h[(size_t)NTOK * FFDIM];   // 268 MB intermediate h

// ---------------- small kernels ---------------------------------------------
__global__ void router_kernel(const float* __restrict__ x,
                              const float* __restrict__ gw) {
    int n = blockIdx.x;
    const float* xr = x + (size_t)n * DMODEL;
    float acc[NEXP];
#pragma unroll
    for (int e = 0; e < NEXP; e++) acc[e] = 0.f;
    for (int d = threadIdx.x; d < DMODEL; d += 256) {
        float xv = xr[d];
#pragma unroll
        for (int e = 0; e < NEXP; e++)
            acc[e] = fmaf(xv, gw[e * DMODEL + d], acc[e]);
    }
#pragma unroll
    for (int e = 0; e < NEXP; e++)
#pragma unroll
        for (int off = 16; off; off >>= 1)
            acc[e] += __shfl_xor_sync(0xffffffffu, acc[e], off);

    __shared__ float red[NEXP][8];
    int w = threadIdx.x >> 5, lane = threadIdx.x & 31;
    if (lane == 0) {
#pragma unroll
        for (int e = 0; e < NEXP; e++) red[e][w] = acc[e];
    }
    __syncthreads();
    if (threadIdx.x < NEXP) {
        float s = 0.f;
#pragma unroll
        for (int ww = 0; ww < 8; ww++) s += red[threadIdx.x][ww];
        g_logits[n * NEXP + threadIdx.x] = s;
    }
}

__global__ void sum_kernel() {
    int e = blockIdx.x;
    float s = 0.f;
    for (int n = threadIdx.x; n < NTOK; n += blockDim.x)
        s += g_logits[n * NEXP + e];
    __shared__ float sm[256];
    sm[threadIdx.x] = s;
    __syncthreads();
    for (int off = 128; off; off >>= 1) {
        if (threadIdx.x < off) sm[threadIdx.x] += sm[threadIdx.x + off];
        __syncthreads();
    }
    if (threadIdx.x == 0) g_sums[e] = sm[0];
}

__global__ void topk_kernel() {
    if (threadIdx.x == 0) {
        int b = 0;
        for (int i = 1; i < NEXP; i++)
            if (g_sums[i] > g_sums[b]) b = i;     // strict > : lower idx on tie
        int s = (b == 0) ? 1 : 0;
        for (int i = 0; i < NEXP; i++)
            if (i != b && g_sums[i] > g_sums[s]) s = i;
        g_sel[0] = b;
        g_sel[1] = s;
    }
}

__global__ void rw_kernel() {
    int n = blockIdx.x * blockDim.x + threadIdx.x;
    if (n >= NTOK) return;
    int s0 = g_sel[0], s1 = g_sel[1];
    float l0 = g_logits[n * NEXP + s0];
    float l1 = g_logits[n * NEXP + s1];
    float m  = fmaxf(l0, l1);
    float e0 = expf(l0 - m), e1 = expf(l1 - m);
    float inv = 1.0f / (e0 + e1);
    g_rw[n * TOPK + 0] = e0 * inv;
    g_rw[n * TOPK + 1] = e1 * inv;
}

// ---------------- tf32 GEMM -------------------------------------------------
#define BM 128
#define BN 128
#define BK 32
#define ASTR 40    // (BK+8): stride%32==8 -> conflict-free fragment loads
#define BSTR 136   // (BN+8)

__device__ __forceinline__ float to_tf32(float x) {
    uint32_t u;
    asm volatile("cvt.rna.tf32.f32 %0, %1;" : "=r"(u) : "f"(x));
    return __uint_as_float(u);
}

__device__ __forceinline__ void mma_tf32(float* c, const float* a, const float* b) {
    const uint32_t* A = reinterpret_cast<const uint32_t*>(a);
    const uint32_t* B = reinterpret_cast<const uint32_t*>(b);
    asm volatile(
        "mma.sync.aligned.m16n8k8.row.col.f32.tf32.tf32.f32 "
        "{%0,%1,%2,%3}, {%4,%5,%6,%7}, {%8,%9}, {%0,%1,%2,%3};\n"
        : "+f"(c[0]), "+f"(c[1]), "+f"(c[2]), "+f"(c[3])
        : "r"(A[0]), "r"(A[1]), "r"(A[2]), "r"(A[3]), "r"(B[0]), "r"(B[1]));
}

__device__ __forceinline__ float gelu_tanh(float x) {
    // jax.nn.gelu default: approximate=True (tanh form)
    float x3 = x * x * x;
    float t  = tanhf(0.7978845608028654f * (x + 0.044715f * x3));
    return 0.5f * x * (1.0f + t);
}

// MODE 0: C = gelu(A@W + bias)         (h production, C row stride = N)
// MODE 1: C = rw[:,kidx] * (A@W+bias)  (first expert output)
// MODE 2: C += rw[:,kidx] * (A@W+bias) (second expert accumulate)
template <int MODE>
__global__ void __launch_bounds__(256)
moe_gemm(const float* __restrict__ A,
         const float* __restrict__ Wall,
         const float* __restrict__ Ball,
         int kidx, int N, int K,
         float* __restrict__ C) {
    __shared__ float As[BM * ASTR];
    __shared__ float Bs[BK * BSTR];

    const int tid  = threadIdx.x;
    const int lane = tid & 31;
    const int wid  = tid >> 5;
    const int g    = lane >> 2;     // group id 0..7
    const int tg   = lane & 3;      // thread-in-group 0..3
    const int wm   = wid & 1;       // warp row 0..1  (64 rows each)
    const int wn   = wid >> 1;      // warp col 0..3  (32 cols each)
    const int m0   = blockIdx.y * BM;
    const int n0   = blockIdx.x * BN;

    const int e = g_sel[kidx];
    const float* Bmat = Wall + (size_t)e * K * N;
    const float* bias = Ball + (size_t)e * N;

    float acc[4][4][4];
#pragma unroll
    for (int i = 0; i < 4; i++)
#pragma unroll
        for (int j = 0; j < 4; j++)
#pragma unroll
            for (int r = 0; r < 4; r++) acc[i][j][r] = 0.f;

    const int KT = K / BK;
    float4 pa[4], pb[4];

    // prologue: load + store tile 0
#pragma unroll
    for (int i = 0; i < 4; i++) {
        int idx = tid + i * 256;
        int r = idx >> 3, c = (idx & 7) << 2;
        pa[i] = *reinterpret_cast<const float4*>(A + (size_t)(m0 + r) * K + c);
        int rb = idx >> 5, cb = (idx & 31) << 2;
        pb[i] = *reinterpret_cast<const float4*>(Bmat + (size_t)rb * N + n0 + cb);
    }
#pragma unroll
    for (int i = 0; i < 4; i++) {
        int idx = tid + i * 256;
        int r = idx >> 3, c = (idx & 7) << 2;
        float4 v;
        v.x = to_tf32(pa[i].x); v.y = to_tf32(pa[i].y);
        v.z = to_tf32(pa[i].z); v.w = to_tf32(pa[i].w);
        *reinterpret_cast<float4*>(&As[r * ASTR + c]) = v;
        int rb = idx >> 5, cb = (idx & 31) << 2;
        float4 w;
        w.x = to_tf32(pb[i].x); w.y = to_tf32(pb[i].y);
        w.z = to_tf32(pb[i].z); w.w = to_tf32(pb[i].w);
        *reinterpret_cast<float4*>(&Bs[rb * BSTR + cb]) = w;
    }
    __syncthreads();

    for (int kt = 0; kt < KT; kt++) {
        if (kt + 1 < KT) {
            int k0 = (kt + 1) * BK;
#pragma unroll
            for (int i = 0; i < 4; i++) {
                int idx = tid + i * 256;
                int r = idx >> 3, c = (idx & 7) << 2;
                pa[i] = *reinterpret_cast<const float4*>(
                    A + (size_t)(m0 + r) * K + k0 + c);
                int rb = idx >> 5, cb = (idx & 31) << 2;
                pb[i] = *reinterpret_cast<const float4*>(
                    Bmat + (size_t)(k0 + rb) * N + n0 + cb);
            }
        }

#pragma unroll
        for (int ks = 0; ks < 4; ks++) {
            const int kk = ks * 8;
            float af[4][4], bf[4][2];
#pragma unroll
            for (int mt = 0; mt < 4; mt++) {
                int row = wm * 64 + mt * 16;
                af[mt][0] = As[(row + g)     * ASTR + kk + tg];
                af[mt][1] = As[(row + g + 8) * ASTR + kk + tg];
                af[mt][2] = As[(row + g)     * ASTR + kk + tg + 4];
                af[mt][3] = As[(row + g + 8) * ASTR + kk + tg + 4];
            }
#pragma unroll
            for (int nt = 0; nt < 4; nt++) {
                int col = wn * 32 + nt * 8;
                bf[nt][0] = Bs[(kk + tg)     * BSTR + col + g];
                bf[nt][1] = Bs[(kk + tg + 4) * BSTR + col + g];
            }
#pragma unroll
            for (int mt = 0; mt < 4; mt++)
#pragma unroll
                for (int nt = 0; nt < 4; nt++)
                    mma_tf32(acc[mt][nt], af[mt], bf[nt]);
        }

        if (kt + 1 < KT) {
            __syncthreads();
#pragma unroll
            for (int i = 0; i < 4; i++) {
                int idx = tid + i * 256;
                int r = idx >> 3, c = (idx & 7) << 2;
                float4 v;
                v.x = to_tf32(pa[i].x); v.y = to_tf32(pa[i].y);
                v.z = to_tf32(pa[i].z); v.w = to_tf32(pa[i].w);
                *reinterpret_cast<float4*>(&As[r * ASTR + c]) = v;
                int rb = idx >> 5, cb = (idx & 31) << 2;
                float4 w;
                w.x = to_tf32(pb[i].x); w.y = to_tf32(pb[i].y);
                w.z = to_tf32(pb[i].z); w.w = to_tf32(pb[i].w);
                *reinterpret_cast<float4*>(&Bs[rb * BSTR + cb]) = w;
            }
            __syncthreads();
        }
    }

    // epilogue
#pragma unroll
    for (int mt = 0; mt < 4; mt++) {
        int r0 = m0 + wm * 64 + mt * 16 + g;
        float w0 = 0.f, w1 = 0.f;
        if (MODE != 0) {
            w0 = g_rw[(size_t)r0 * TOPK + kidx];
            w1 = g_rw[(size_t)(r0 + 8) * TOPK + kidx];
        }
#pragma unroll
        for (int nt = 0; nt < 4; nt++) {
            int cc = n0 + wn * 32 + nt * 8 + tg * 2;
            const float* cr = acc[mt][nt];
            float b0 = bias[cc], b1v = bias[cc + 1];
            float y00 = cr[0] + b0, y01 = cr[1] + b1v;
            float y10 = cr[2] + b0, y11 = cr[3] + b1v;
            float* p0 = C + (size_t)r0 * N + cc;
            float* p1 = C + (size_t)(r0 + 8) * N + cc;
            if (MODE == 0) {
                float2 o0 = {gelu_tanh(y00), gelu_tanh(y01)};
                float2 o1 = {gelu_tanh(y10), gelu_tanh(y11)};
                *reinterpret_cast<float2*>(p0) = o0;
                *reinterpret_cast<float2*>(p1) = o1;
            } else if (MODE == 1) {
                float2 o0 = {w0 * y00, w0 * y01};
                float2 o1 = {w1 * y10, w1 * y11};
                *reinterpret_cast<float2*>(p0) = o0;
                *reinterpret_cast<float2*>(p1) = o1;
            } else {
                float2 c0 = *reinterpret_cast<float2*>(p0);
                float2 c1 = *reinterpret_cast<float2*>(p1);
                c0.x += w0 * y00; c0.y += w0 * y01;
                c1.x += w1 * y10; c1.y += w1 * y11;
                *reinterpret_cast<float2*>(p0) = c0;
                *reinterpret_cast<float2*>(p1) = c1;
            }
        }
    }
}

// ---------------- launch -----------------------------------------------------
extern "C" void kernel_launch(void* const* d_in, const int* in_sizes, int n_in,
                              void* d_out, int out_size) {
    const float* x  = (const float*)d_in[0];   // [B,S,D] -> [8192,2048]
    const float* gw = (const float*)d_in[1];   // [8,2048]
    const float* w1 = (const float*)d_in[2];   // [8,2048,8192]
    const float* b1 = (const float*)d_in[3];   // [8,8192]
    const float* w2 = (const float*)d_in[4];   // [8,8192,2048]
    const float* b2 = (const float*)d_in[5];   // [8,2048]
    float* out = (float*)d_out;                // [8192,2048]

    float* hptr = nullptr;
    cudaGetSymbolAddress((void**)&hptr, g_h);

    router_kernel<<<NTOK, 256>>>(x, gw);
    sum_kernel<<<NEXP, 256>>>();
    topk_kernel<<<1, 32>>>();
    rw_kernel<<<NTOK / 256, 256>>>();

    dim3 blk(256);
    dim3 g1(FFDIM / BN, NTOK / BM);   // (64,64)
    dim3 g2(DMODEL / BN, NTOK / BM);  // (16,64)

    // expert 0
    moe_gemm<0><<<g1, blk>>>(x,    w1, b1, 0, FFDIM,  DMODEL, hptr);
    moe_gemm<1><<<g2, blk>>>(hptr, w2, b2, 0, DMODEL, FFDIM,  out);
    // expert 1
    moe_gemm<0><<<g1, blk>>>(x,    w1, b1, 1, FFDIM,  DMODEL, hptr);
    moe_gemm<2><<<g2, blk>>>(hptr, w2, b2, 1, DMODEL, FFDIM,  out);
}

// round 3
// speedup vs baseline: 1.1599x; 1.1599x over previous
#include <cuda_runtime.h>
#include <cstdint>

// Problem constants (B=2, S=4096, D=2048, E=8, DFF=8192, TOP_K=2)
#define NTOK   8192
#define DMODEL 2048
#define NEXP   8
#define FFDIM  8192
#define TOPK   2

// ---------------- device scratch (allocation-free rule: __device__ globals) --
__device__ float g_logits[NTOK * NEXP];
__device__ float g_sums[NEXP];
__device__ int   g_sel[TOPK];
__device__ float g_rw[NTOK * TOPK];
__device__ float g_h[(size_t)NTOK * FFDIM];          // 268 MB intermediate h (tf32-rounded)
__device__ float g_xc[(size_t)NTOK * DMODEL];        // 67 MB  x in tf32
__device__ float g_w1c[2][(size_t)DMODEL * FFDIM];   // 2*67 MB selected w1 in tf32
__device__ float g_w2c[2][(size_t)FFDIM * DMODEL];   // 2*67 MB selected w2 in tf32

// ---------------- helpers ----------------------------------------------------
__device__ __forceinline__ float to_tf32(float x) {
    uint32_t u;
    asm volatile("cvt.rna.tf32.f32 %0, %1;" : "=r"(u) : "f"(x));
    return __uint_as_float(u);
}

__device__ __forceinline__ void cp16(void* smem, const void* gmem) {
    uint32_t s = (uint32_t)__cvta_generic_to_shared(smem);
    asm volatile("cp.async.cg.shared.global [%0], [%1], 16;\n" :: "r"(s), "l"(gmem));
}
__device__ __forceinline__ void cp_commit() {
    asm volatile("cp.async.commit_group;\n" ::: "memory");
}
template <int N>
__device__ __forceinline__ void cp_wait() {
    asm volatile("cp.async.wait_group %0;\n" :: "n"(N) : "memory");
}

// ---------------- small kernels ---------------------------------------------
__global__ void router_kernel(const float* __restrict__ x,
                              const float* __restrict__ gw) {
    int n = blockIdx.x;
    const float* xr = x + (size_t)n * DMODEL;
    float acc[NEXP];
#pragma unroll
    for (int e = 0; e < NEXP; e++) acc[e] = 0.f;
    for (int d = threadIdx.x; d < DMODEL; d += 256) {
        float xv = xr[d];
#pragma unroll
        for (int e = 0; e < NEXP; e++)
            acc[e] = fmaf(xv, gw[e * DMODEL + d], acc[e]);
    }
#pragma unroll
    for (int e = 0; e < NEXP; e++)
#pragma unroll
        for (int off = 16; off; off >>= 1)
            acc[e] += __shfl_xor_sync(0xffffffffu, acc[e], off);

    __shared__ float red[NEXP][8];
    int w = threadIdx.x >> 5, lane = threadIdx.x & 31;
    if (lane == 0) {
#pragma unroll
        for (int e = 0; e < NEXP; e++) red[e][w] = acc[e];
    }
    __syncthreads();
    if (threadIdx.x < NEXP) {
        float s = 0.f;
#pragma unroll
        for (int ww = 0; ww < 8; ww++) s += red[threadIdx.x][ww];
        g_logits[n * NEXP + threadIdx.x] = s;
    }
}

__global__ void sum_kernel() {
    int e = blockIdx.x;
    float s = 0.f;
    for (int n = threadIdx.x; n < NTOK; n += blockDim.x)
        s += g_logits[n * NEXP + e];
    __shared__ float sm[256];
    sm[threadIdx.x] = s;
    __syncthreads();
    for (int off = 128; off; off >>= 1) {
        if (threadIdx.x < off) sm[threadIdx.x] += sm[threadIdx.x + off];
        __syncthreads();
    }
    if (threadIdx.x == 0) g_sums[e] = sm[0];
}

__global__ void topk_kernel() {
    if (threadIdx.x == 0) {
        int b = 0;
        for (int i = 1; i < NEXP; i++)
            if (g_sums[i] > g_sums[b]) b = i;     // strict > : lower idx on tie
        int s = (b == 0) ? 1 : 0;
        for (int i = 0; i < NEXP; i++)
            if (i != b && g_sums[i] > g_sums[s]) s = i;
        g_sel[0] = b;
        g_sel[1] = s;
    }
}

__global__ void rw_kernel() {
    int n = blockIdx.x * blockDim.x + threadIdx.x;
    if (n >= NTOK) return;
    int s0 = g_sel[0], s1 = g_sel[1];
    float l0 = g_logits[n * NEXP + s0];
    float l1 = g_logits[n * NEXP + s1];
    float m  = fmaxf(l0, l1);
    float e0 = expf(l0 - m), e1 = expf(l1 - m);
    float inv = 1.0f / (e0 + e1);
    g_rw[n * TOPK + 0] = e0 * inv;
    g_rw[n * TOPK + 1] = e1 * inv;
}

// Convert a plain fp32 array to tf32-rounded fp32 (vectorized, grid-stride)
__global__ void cvt_x_kernel(const float4* __restrict__ src,
                             float4* __restrict__ dst, size_t n4) {
    for (size_t i = (size_t)blockIdx.x * blockDim.x + threadIdx.x; i < n4;
         i += (size_t)gridDim.x * blockDim.x) {
        float4 v = src[i];
        v.x = to_tf32(v.x); v.y = to_tf32(v.y);
        v.z = to_tf32(v.z); v.w = to_tf32(v.w);
        dst[i] = v;
    }
}

// Convert selected expert's weight matrix to tf32-rounded fp32
__global__ void cvt_w_kernel(const float* __restrict__ Wall,
                             float* __restrict__ dst, int kidx, size_t elems) {
    int e = g_sel[kidx];
    const float4* s = reinterpret_cast<const float4*>(Wall + (size_t)e * elems);
    float4* d = reinterpret_cast<float4*>(dst);
    size_t n4 = elems >> 2;
    for (size_t i = (size_t)blockIdx.x * blockDim.x + threadIdx.x; i < n4;
         i += (size_t)gridDim.x * blockDim.x) {
        float4 v = s[i];
        v.x = to_tf32(v.x); v.y = to_tf32(v.y);
        v.z = to_tf32(v.z); v.w = to_tf32(v.w);
        d[i] = v;
    }
}

// ---------------- tf32 GEMM (cp.async 3-stage pipeline) ----------------------
#define BM 128
#define BN 128
#define BK 32
#define ASTR 40     // (BK+8): stride%32==8 -> conflict-free fragment loads
#define BSTR 136    // (BN+8)
#define NSTAGE 3
#define A_TILE (BM * ASTR)
#define B_TILE (BK * BSTR)
#define SMEM_BYTES (NSTAGE * (A_TILE + B_TILE) * 4)

__device__ __forceinline__ void mma_tf32(float* c, const float* a, const float* b) {
    const uint32_t* A = reinterpret_cast<const uint32_t*>(a);
    const uint32_t* B = reinterpret_cast<const uint32_t*>(b);
    asm volatile(
        "mma.sync.aligned.m16n8k8.row.col.f32.tf32.tf32.f32 "
        "{%0,%1,%2,%3}, {%4,%5,%6,%7}, {%8,%9}, {%0,%1,%2,%3};\n"
        : "+f"(c[0]), "+f"(c[1]), "+f"(c[2]), "+f"(c[3])
        : "r"(A[0]), "r"(A[1]), "r"(A[2]), "r"(A[3]), "r"(B[0]), "r"(B[1]));
}

__device__ __forceinline__ float gelu_tanh(float x) {
    float x3 = x * x * x;
    float t  = tanhf(0.7978845608028654f * (x + 0.044715f * x3));
    return 0.5f * x * (1.0f + t);
}

// MODE 0: C = tf32(gelu(A@W + bias))   (h production)
// MODE 1: C = rw[:,kidx] * (A@W+bias)
// MODE 2: C += rw[:,kidx] * (A@W+bias)
template <int MODE>
__global__ void __launch_bounds__(256, 1)
moe_gemm(const float* __restrict__ A,
         const float* __restrict__ Bmat,      // pre-converted, [K,N] row-major
         const float* __restrict__ Ball,      // bias table [E,N]
         int kidx, int N, int K,
         float* __restrict__ C) {
    extern __shared__ float smem[];
    float* As = smem;                     // NSTAGE * A_TILE
    float* Bs = smem + NSTAGE * A_TILE;   // NSTAGE * B_TILE

    const int tid  = threadIdx.x;
    const int lane = tid & 31;
    const int wid  = tid >> 5;
    const int g    = lane >> 2;
    const int tg   = lane & 3;
    const int wm   = wid & 1;
    const int wn   = wid >> 1;
    const int m0   = blockIdx.y * BM;
    const int n0   = blockIdx.x * BN;

    const int e = g_sel[kidx];
    const float* bias = Ball + (size_t)e * N;

    // per-thread copy coordinates (8 x 16B per stage)
    const int ar = tid >> 3;            // 0..127  (wait, 256 threads: tid>>3 = 0..31) -- see loop
    const int ac = (tid & 7) << 2;
    const int br = tid >> 5;            // 0..7
    const int bc = (tid & 31) << 2;
    (void)ar;

    float acc[4][4][4];
#pragma unroll
    for (int i = 0; i < 4; i++)
#pragma unroll
        for (int j = 0; j < 4; j++)
#pragma unroll
            for (int r = 0; r < 4; r++) acc[i][j][r] = 0.f;

    const int KT = K / BK;

    auto issue_stage = [&](int s, int kt) {
        const int k0 = kt * BK;
        float* as = As + s * A_TILE;
        float* bs = Bs + s * B_TILE;
#pragma unroll
        for (int i = 0; i < 4; i++) {
            int idx = tid + i * 256;
            int r = idx >> 3, c = (idx & 7) << 2;       // r:0..127, c:0..28
            cp16(&as[r * ASTR + c], A + (size_t)(m0 + r) * K + k0 + c);
            int rb = idx >> 5, cb = (idx & 31) << 2;    // rb:0..31, cb:0..124
            cp16(&bs[rb * BSTR + cb], Bmat + (size_t)(k0 + rb) * N + n0 + cb);
        }
    };

    // prologue: stages 0 and 1
    issue_stage(0, 0); cp_commit();
    if (KT > 1) issue_stage(1, 1);
    cp_commit();

    for (int kt = 0; kt < KT; kt++) {
        cp_wait<1>();
        __syncthreads();

        if (kt + 2 < KT) issue_stage((kt + 2) % NSTAGE, kt + 2);
        cp_commit();

        const float* as = As + (kt % NSTAGE) * A_TILE;
        const float* bs = Bs + (kt % NSTAGE) * B_TILE;

#pragma unroll
        for (int ks = 0; ks < 4; ks++) {
            const int kk = ks * 8;
            float af[4][4], bf[4][2];
#pragma unroll
            for (int mt = 0; mt < 4; mt++) {
                int row = wm * 64 + mt * 16;
                af[mt][0] = as[(row + g)     * ASTR + kk + tg];
                af[mt][1] = as[(row + g + 8) * ASTR + kk + tg];
                af[mt][2] = as[(row + g)     * ASTR + kk + tg + 4];
                af[mt][3] = as[(row + g + 8) * ASTR + kk + tg + 4];
            }
#pragma unroll
            for (int nt = 0; nt < 4; nt++) {
                int col = wn * 32 + nt * 8;
                bf[nt][0] = bs[(kk + tg)     * BSTR + col + g];
                bf[nt][1] = bs[(kk + tg + 4) * BSTR + col + g];
            }
#pragma unroll
            for (int mt = 0; mt < 4; mt++)
#pragma unroll
                for (int nt = 0; nt < 4; nt++)
                    mma_tf32(acc[mt][nt], af[mt], bf[nt]);
        }
        // next iteration's __syncthreads() protects the stage we overwrite
    }

    // epilogue
#pragma unroll
    for (int mt = 0; mt < 4; mt++) {
        int r0 = m0 + wm * 64 + mt * 16 + g;
        float w0 = 0.f, w1 = 0.f;
        if (MODE != 0) {
            w0 = g_rw[(size_t)r0 * TOPK + kidx];
            w1 = g_rw[(size_t)(r0 + 8) * TOPK + kidx];
        }
#pragma unroll
        for (int nt = 0; nt < 4; nt++) {
            int cc = n0 + wn * 32 + nt * 8 + tg * 2;
            const float* cr = acc[mt][nt];
            float b0 = bias[cc], b1v = bias[cc + 1];
            float y00 = cr[0] + b0, y01 = cr[1] + b1v;
            float y10 = cr[2] + b0, y11 = cr[3] + b1v;
            float* p0 = C + (size_t)r0 * N + cc;
            float* p1 = C + (size_t)(r0 + 8) * N + cc;
            if (MODE == 0) {
                float2 o0 = {to_tf32(gelu_tanh(y00)), to_tf32(gelu_tanh(y01))};
                float2 o1 = {to_tf32(gelu_tanh(y10)), to_tf32(gelu_tanh(y11))};
                *reinterpret_cast<float2*>(p0) = o0;
                *reinterpret_cast<float2*>(p1) = o1;
            } else if (MODE == 1) {
                float2 o0 = {w0 * y00, w0 * y01};
                float2 o1 = {w1 * y10, w1 * y11};
                *reinterpret_cast<float2*>(p0) = o0;
                *reinterpret_cast<float2*>(p1) = o1;
            } else {
                float2 c0 = *reinterpret_cast<float2*>(p0);
                float2 c1 = *reinterpret_cast<float2*>(p1);
                c0.x += w0 * y00; c0.y += w0 * y01;
                c1.x += w1 * y10; c1.y += w1 * y11;
                *reinterpret_cast<float2*>(p0) = c0;
                *reinterpret_cast<float2*>(p1) = c1;
            }
        }
    }
}

// ---------------- launch -----------------------------------------------------
extern "C" void kernel_launch(void* const* d_in, const int* in_sizes, int n_in,
                              void* d_out, int out_size) {
    const float* x  = (const float*)d_in[0];   // [8192,2048]
    const float* gw = (const float*)d_in[1];   // [8,2048]
    const float* w1 = (const float*)d_in[2];   // [8,2048,8192]
    const float* b1 = (const float*)d_in[3];   // [8,8192]
    const float* w2 = (const float*)d_in[4];   // [8,8192,2048]
    const float* b2 = (const float*)d_in[5];   // [8,2048]
    float* out = (float*)d_out;                // [8192,2048]

    float *hptr, *xc, *w1c0, *w1c1, *w2c0, *w2c1;
    cudaGetSymbolAddress((void**)&hptr, g_h);
    cudaGetSymbolAddress((void**)&xc,   g_xc);
    cudaGetSymbolAddress((void**)&w1c0, g_w1c);
    cudaGetSymbolAddress((void**)&w2c0, g_w2c);
    w1c1 = w1c0 + (size_t)DMODEL * FFDIM;
    w2c1 = w2c0 + (size_t)FFDIM * DMODEL;

    cudaFuncSetAttribute(moe_gemm<0>, cudaFuncAttributeMaxDynamicSharedMemorySize, SMEM_BYTES);
    cudaFuncSetAttribute(moe_gemm<1>, cudaFuncAttributeMaxDynamicSharedMemorySize, SMEM_BYTES);
    cudaFuncSetAttribute(moe_gemm<2>, cudaFuncAttributeMaxDynamicSharedMemorySize, SMEM_BYTES);

    router_kernel<<<NTOK, 256>>>(x, gw);
    sum_kernel<<<NEXP, 256>>>();
    topk_kernel<<<1, 32>>>();
    rw_kernel<<<NTOK / 256, 256>>>();

    // pre-convert operands to tf32
    size_t xel = (size_t)NTOK * DMODEL;
    cvt_x_kernel<<<2048, 256>>>((const float4*)x, (float4*)xc, xel >> 2);
    size_t wel = (size_t)DMODEL * FFDIM;
    cvt_w_kernel<<<4096, 256>>>(w1, w1c0, 0, wel);
    cvt_w_kernel<<<4096, 256>>>(w1, w1c1, 1, wel);
    cvt_w_kernel<<<4096, 256>>>(w2, w2c0, 0, wel);
    cvt_w_kernel<<<4096, 256>>>(w2, w2c1, 1, wel);

    dim3 blk(256);
    dim3 g1(FFDIM / BN, NTOK / BM);   // (64,64)
    dim3 g2(DMODEL / BN, NTOK / BM);  // (16,64)

    moe_gemm<0><<<g1, blk, SMEM_BYTES>>>(xc,   w1c0, b1, 0, FFDIM,  DMODEL, hptr);
    moe_gemm<1><<<g2, blk, SMEM_BYTES>>>(hptr, w2c0, b2, 0, DMODEL, FFDIM,  out);
    moe_gemm<0><<<g1, blk, SMEM_BYTES>>>(xc,   w1c1, b1, 1, FFDIM,  DMODEL, hptr);
    moe_gemm<2><<<g2, blk, SMEM_BYTES>>>(hptr, w2c1, b2, 1, DMODEL, FFDIM,  out);
}

// round 5
// speedup vs baseline: 1.3955x; 1.2031x over previous
#include <cuda_runtime.h>
#include <cstdint>

// Problem constants (B=2, S=4096, D=2048, E=8, DFF=8192, TOP_K=2)
#define NTOK   8192
#define DMODEL 2048
#define NEXP   8
#define FFDIM  8192
#define TOPK   2

// ---------------- device scratch (allocation-free rule: __device__ globals) --
__device__ float g_logits[NTOK * NEXP];
__device__ float g_sums[NEXP];
__device__ int   g_sel[TOPK];
__device__ float g_rw[NTOK * TOPK];
__device__ float g_h[(size_t)NTOK * FFDIM];          // h (tf32-rounded)
__device__ float g_xc[(size_t)NTOK * DMODEL];        // x in tf32
__device__ float g_w1c[2][(size_t)DMODEL * FFDIM];   // selected w1 tf32 [K,N]
__device__ float g_w2c[2][(size_t)FFDIM * DMODEL];   // selected w2 tf32 [K,N]

// ---------------- helpers ----------------------------------------------------
__device__ __forceinline__ float to_tf32(float x) {
    uint32_t u;
    asm volatile("cvt.rna.tf32.f32 %0, %1;" : "=r"(u) : "f"(x));
    return __uint_as_float(u);
}

__device__ __forceinline__ void cp16(void* smem, const void* gmem) {
    uint32_t s = (uint32_t)__cvta_generic_to_shared(smem);
    asm volatile("cp.async.cg.shared.global [%0], [%1], 16;\n" :: "r"(s), "l"(gmem));
}
__device__ __forceinline__ void cp_commit() {
    asm volatile("cp.async.commit_group;\n" ::: "memory");
}
template <int N>
__device__ __forceinline__ void cp_wait() {
    asm volatile("cp.async.wait_group %0;\n" :: "n"(N) : "memory");
}

// ---------------- small kernels ---------------------------------------------
__global__ void router_kernel(const float* __restrict__ x,
                              const float* __restrict__ gw) {
    int n = blockIdx.x;
    const float* xr = x + (size_t)n * DMODEL;
    float acc[NEXP];
#pragma unroll
    for (int e = 0; e < NEXP; e++) acc[e] = 0.f;
    for (int d = threadIdx.x; d < DMODEL; d += 256) {
        float xv = xr[d];
#pragma unroll
        for (int e = 0; e < NEXP; e++)
            acc[e] = fmaf(xv, gw[e * DMODEL + d], acc[e]);
    }
#pragma unroll
    for (int e = 0; e < NEXP; e++)
#pragma unroll
        for (int off = 16; off; off >>= 1)
            acc[e] += __shfl_xor_sync(0xffffffffu, acc[e], off);

    __shared__ float red[NEXP][8];
    int w = threadIdx.x >> 5, lane = threadIdx.x & 31;
    if (lane == 0) {
#pragma unroll
        for (int e = 0; e < NEXP; e++) red[e][w] = acc[e];
    }
    __syncthreads();
    if (threadIdx.x < NEXP) {
        float s = 0.f;
#pragma unroll
        for (int ww = 0; ww < 8; ww++) s += red[threadIdx.x][ww];
        g_logits[n * NEXP + threadIdx.x] = s;
    }
}

__global__ void sum_kernel() {
    int e = blockIdx.x;
    float s = 0.f;
    for (int n = threadIdx.x; n < NTOK; n += blockDim.x)
        s += g_logits[n * NEXP + e];
    __shared__ float sm[256];
    sm[threadIdx.x] = s;
    __syncthreads();
    for (int off = 128; off; off >>= 1) {
        if (threadIdx.x < off) sm[threadIdx.x] += sm[threadIdx.x + off];
        __syncthreads();
    }
    if (threadIdx.x == 0) g_sums[e] = sm[0];
}

__global__ void topk_kernel() {
    if (threadIdx.x == 0) {
        int b = 0;
        for (int i = 1; i < NEXP; i++)
            if (g_sums[i] > g_sums[b]) b = i;     // strict > : lower idx on tie
        int s = (b == 0) ? 1 : 0;
        for (int i = 0; i < NEXP; i++)
            if (i != b && g_sums[i] > g_sums[s]) s = i;
        g_sel[0] = b;
        g_sel[1] = s;
    }
}

__global__ void rw_kernel() {
    int n = blockIdx.x * blockDim.x + threadIdx.x;
    if (n >= NTOK) return;
    int s0 = g_sel[0], s1 = g_sel[1];
    float l0 = g_logits[n * NEXP + s0];
    float l1 = g_logits[n * NEXP + s1];
    float m  = fmaxf(l0, l1);
    float e0 = expf(l0 - m), e1 = expf(l1 - m);
    float inv = 1.0f / (e0 + e1);
    g_rw[n * TOPK + 0] = e0 * inv;
    g_rw[n * TOPK + 1] = e1 * inv;
}

__global__ void cvt_x_kernel(const float4* __restrict__ src,
                             float4* __restrict__ dst, size_t n4) {
    for (size_t i = (size_t)blockIdx.x * blockDim.x + threadIdx.x; i < n4;
         i += (size_t)gridDim.x * blockDim.x) {
        float4 v = src[i];
        v.x = to_tf32(v.x); v.y = to_tf32(v.y);
        v.z = to_tf32(v.z); v.w = to_tf32(v.w);
        dst[i] = v;
    }
}

__global__ void cvt_w_kernel(const float* __restrict__ Wall,
                             float* __restrict__ dst, int kidx, size_t elems) {
    int e = g_sel[kidx];
    const float4* s = reinterpret_cast<const float4*>(Wall + (size_t)e * elems);
    float4* d = reinterpret_cast<float4*>(dst);
    size_t n4 = elems >> 2;
    for (size_t i = (size_t)blockIdx.x * blockDim.x + threadIdx.x; i < n4;
         i += (size_t)gridDim.x * blockDim.x) {
        float4 v = s[i];
        v.x = to_tf32(v.x); v.y = to_tf32(v.y);
        v.z = to_tf32(v.z); v.w = to_tf32(v.w);
        d[i] = v;
    }
}

// ---------------- tf32 GEMM: 128x256 CTA, 64x64 warp, cp.async 3-stage -------
#define BM 128
#define BN 256
#define BK 32
#define ASTR 40     // BK+8  (stride%32==8 -> conflict-free)
#define BSTR 264    // BN+8
#define NSTAGE 3
#define A_TILE (BM * ASTR)     // floats
#define B_TILE (BK * BSTR)
#define SMEM_BYTES (NSTAGE * (A_TILE + B_TILE) * 4)

__device__ __forceinline__ void mma_tf32(float* c, const float* a, const float* b) {
    const uint32_t* A = reinterpret_cast<const uint32_t*>(a);
    const uint32_t* B = reinterpret_cast<const uint32_t*>(b);
    asm volatile(
        "mma.sync.aligned.m16n8k8.row.col.f32.tf32.tf32.f32 "
        "{%0,%1,%2,%3}, {%4,%5,%6,%7}, {%8,%9}, {%0,%1,%2,%3};\n"
        : "+f"(c[0]), "+f"(c[1]), "+f"(c[2]), "+f"(c[3])
        : "r"(A[0]), "r"(A[1]), "r"(A[2]), "r"(A[3]), "r"(B[0]), "r"(B[1]));
}

__device__ __forceinline__ float gelu_tanh(float x) {
    float x3 = x * x * x;
    float t  = tanhf(0.7978845608028654f * (x + 0.044715f * x3));
    return 0.5f * x * (1.0f + t);
}

// MODE 0: C = tf32(gelu(A@W + bias))   (h production)
// MODE 1: C = rw[:,kidx] * (A@W+bias)
// MODE 2: C += rw[:,kidx] * (A@W+bias)
template <int MODE>
__global__ void __launch_bounds__(256, 1)
moe_gemm(const float* __restrict__ A,
         const float* __restrict__ Bmat,      // tf32-rounded, [K,N] row-major
         const float* __restrict__ Ball,      // bias table [E,N]
         int kidx, int N, int K,
         float* __restrict__ C) {
    extern __shared__ float smem[];
    float* As = smem;                     // NSTAGE * A_TILE
    float* Bs = smem + NSTAGE * A_TILE;   // NSTAGE * B_TILE

    const int tid  = threadIdx.x;
    const int lane = tid & 31;
    const int wid  = tid >> 5;
    const int g    = lane >> 2;
    const int tg   = lane & 3;
    const int wm   = wid & 1;       // 0..1  (64 rows each)
    const int wn   = wid >> 1;      // 0..3  (64 cols each)
    const int m0   = blockIdx.y * BM;
    const int n0   = blockIdx.x * BN;

    const int e = g_sel[kidx];
    const float* bias = Ball + (size_t)e * N;

    float acc[4][8][4];
#pragma unroll
    for (int i = 0; i < 4; i++)
#pragma unroll
        for (int j = 0; j < 8; j++)
#pragma unroll
            for (int r = 0; r < 4; r++) acc[i][j][r] = 0.f;

    const int KT = K / BK;

    auto issue_stage = [&](int s, int kt) {
        const int k0 = kt * BK;
        float* as = As + s * A_TILE;
        float* bs = Bs + s * B_TILE;
#pragma unroll
        for (int i = 0; i < 4; i++) {              // A: 1024 x 16B chunks
            int idx = tid + i * 256;
            int r = idx >> 3, c = (idx & 7) << 2;
            cp16(&as[r * ASTR + c], A + (size_t)(m0 + r) * K + k0 + c);
        }
#pragma unroll
        for (int i = 0; i < 8; i++) {              // B: 2048 x 16B chunks
            int idx = tid + i * 256;
            int rb = idx >> 6, cb = (idx & 63) << 2;
            cp16(&bs[rb * BSTR + cb], Bmat + (size_t)(k0 + rb) * N + n0 + cb);
        }
    };

    // prologue: stages 0 and 1
    issue_stage(0, 0); cp_commit();
    if (KT > 1) issue_stage(1, 1);
    cp_commit();

    for (int kt = 0; kt < KT; kt++) {
        cp_wait<1>();
        __syncthreads();

        if (kt + 2 < KT) issue_stage((kt + 2) % NSTAGE, kt + 2);
        cp_commit();

        const float* as = As + (kt % NSTAGE) * A_TILE;
        const float* bs = Bs + (kt % NSTAGE) * B_TILE;

#pragma unroll
        for (int ks = 0; ks < 4; ks++) {
            const int kk = ks * 8;
            float af[4][4], bf[8][2];
#pragma unroll
            for (int mt = 0; mt < 4; mt++) {
                int row = wm * 64 + mt * 16;
                af[mt][0] = as[(row + g)     * ASTR + kk + tg];
                af[mt][1] = as[(row + g + 8) * ASTR + kk + tg];
                af[mt][2] = as[(row + g)     * ASTR + kk + tg + 4];
                af[mt][3] = as[(row + g + 8) * ASTR + kk + tg + 4];
            }
#pragma unroll
            for (int nt = 0; nt < 8; nt++) {
                int col = wn * 64 + nt * 8;
                bf[nt][0] = bs[(kk + tg)     * BSTR + col + g];
                bf[nt][1] = bs[(kk + tg + 4) * BSTR + col + g];
            }
#pragma unroll
            for (int mt = 0; mt < 4; mt++)
#pragma unroll
                for (int nt = 0; nt < 8; nt++)
                    mma_tf32(acc[mt][nt], af[mt], bf[nt]);
        }
        // next iteration's __syncthreads() protects the stage being overwritten
    }

    // ---------------- epilogue ----------------
#pragma unroll
    for (int mt = 0; mt < 4; mt++) {
        int r0 = m0 + wm * 64 + mt * 16 + g;
        float w0 = 0.f, w1 = 0.f;
        if (MODE != 0) {
            w0 = g_rw[(size_t)r0 * TOPK + kidx];
            w1 = g_rw[(size_t)(r0 + 8) * TOPK + kidx];
        }
#pragma unroll
        for (int nt = 0; nt < 8; nt++) {
            int cc = n0 + wn * 64 + nt * 8 + tg * 2;
            const float* cr = acc[mt][nt];
            float b0 = bias[cc], b1v = bias[cc + 1];
            float y00 = cr[0] + b0, y01 = cr[1] + b1v;
            float y10 = cr[2] + b0, y11 = cr[3] + b1v;
            float* p0 = C + (size_t)r0 * N + cc;
            float* p1 = C + (size_t)(r0 + 8) * N + cc;
            if (MODE == 0) {
                float2 o0 = {to_tf32(gelu_tanh(y00)), to_tf32(gelu_tanh(y01))};
                float2 o1 = {to_tf32(gelu_tanh(y10)), to_tf32(gelu_tanh(y11))};
                *reinterpret_cast<float2*>(p0) = o0;
                *reinterpret_cast<float2*>(p1) = o1;
            } else if (MODE == 1) {
                float2 o0 = {w0 * y00, w0 * y01};
                float2 o1 = {w1 * y10, w1 * y11};
                *reinterpret_cast<float2*>(p0) = o0;
                *reinterpret_cast<float2*>(p1) = o1;
            } else {
                float2 c0 = *reinterpret_cast<float2*>(p0);
                float2 c1 = *reinterpret_cast<float2*>(p1);
                c0.x += w0 * y00; c0.y += w0 * y01;
                c1.x += w1 * y10; c1.y += w1 * y11;
                *reinterpret_cast<float2*>(p0) = c0;
                *reinterpret_cast<float2*>(p1) = c1;
            }
        }
    }
}

// ---------------- launch -----------------------------------------------------
extern "C" void kernel_launch(void* const* d_in, const int* in_sizes, int n_in,
                              void* d_out, int out_size) {
    const float* x  = (const float*)d_in[0];   // [8192,2048]
    const float* gw = (const float*)d_in[1];   // [8,2048]
    const float* w1 = (const float*)d_in[2];   // [8,2048,8192]
    const float* b1 = (const float*)d_in[3];   // [8,8192]
    const float* w2 = (const float*)d_in[4];   // [8,8192,2048]
    const float* b2 = (const float*)d_in[5];   // [8,2048]
    float* out = (float*)d_out;                // [8192,2048]

    float *hptr, *xc, *w1c0, *w1c1, *w2c0, *w2c1;
    cudaGetSymbolAddress((void**)&hptr, g_h);
    cudaGetSymbolAddress((void**)&xc,   g_xc);
    cudaGetSymbolAddress((void**)&w1c0, g_w1c);
    cudaGetSymbolAddress((void**)&w2c0, g_w2c);
    w1c1 = w1c0 + (size_t)DMODEL * FFDIM;
    w2c1 = w2c0 + (size_t)FFDIM * DMODEL;

    cudaFuncSetAttribute(moe_gemm<0>, cudaFuncAttributeMaxDynamicSharedMemorySize, SMEM_BYTES);
    cudaFuncSetAttribute(moe_gemm<1>, cudaFuncAttributeMaxDynamicSharedMemorySize, SMEM_BYTES);
    cudaFuncSetAttribute(moe_gemm<2>, cudaFuncAttributeMaxDynamicSharedMemorySize, SMEM_BYTES);

    router_kernel<<<NTOK, 256>>>(x, gw);
    sum_kernel<<<NEXP, 256>>>();
    topk_kernel<<<1, 32>>>();
    rw_kernel<<<NTOK / 256, 256>>>();

    // pre-convert operands to tf32 (no transpose: mma B operand is [K,N])
    cvt_x_kernel<<<2048, 256>>>((const float4*)x, (float4*)xc, ((size_t)NTOK * DMODEL) >> 2);
    size_t wel = (size_t)DMODEL * FFDIM;
    cvt_w_kernel<<<4096, 256>>>(w1, w1c0, 0, wel);
    cvt_w_kernel<<<4096, 256>>>(w1, w1c1, 1, wel);
    cvt_w_kernel<<<4096, 256>>>(w2, w2c0, 0, wel);
    cvt_w_kernel<<<4096, 256>>>(w2, w2c1, 1, wel);

    dim3 blk(256);
    dim3 g1(FFDIM / BN, NTOK / BM);   // (32,64)
    dim3 g2(DMODEL / BN, NTOK / BM);  // (8,64)

    moe_gemm<0><<<g1, blk, SMEM_BYTES>>>(xc,   w1c0, b1, 0, FFDIM,  DMODEL, hptr);
    moe_gemm<1><<<g2, blk, SMEM_BYTES>>>(hptr, w2c0, b2, 0, DMODEL, FFDIM,  out);
    moe_gemm<0><<<g1, blk, SMEM_BYTES>>>(xc,   w1c1, b1, 1, FFDIM,  DMODEL, hptr);
    moe_gemm<2><<<g2, blk, SMEM_BYTES>>>(hptr, w2c1, b2, 1, DMODEL, FFDIM,  out);
}

// round 6
// speedup vs baseline: 2.1884x; 1.5681x over previous
#include <cuda_runtime.h>
#include <cuda_fp16.h>
#include <cstdint>

// Problem constants (B=2, S=4096, D=2048, E=8, DFF=8192, TOP_K=2)
#define NTOK   8192
#define DMODEL 2048
#define NEXP   8
#define FFDIM  8192
#define TOPK   2

// ---------------- device scratch (allocation-free rule: __device__ globals) --
__device__ float  g_logits[NTOK * NEXP];
__device__ float  g_sums[NEXP];
__device__ int    g_sel[TOPK];
__device__ float  g_rw[NTOK * TOPK];
__device__ __half g_xh[(size_t)NTOK * DMODEL];        // x  fp16 [M,K]
__device__ __half g_hh[(size_t)NTOK * FFDIM];         // h  fp16 [M,K]
__device__ __half g_w1t[2][(size_t)FFDIM * DMODEL];   // w1^T fp16 [N=FF, K=D]
__device__ __half g_w2t[2][(size_t)DMODEL * FFDIM];   // w2^T fp16 [N=D,  K=FF]

// ---------------- helpers ----------------------------------------------------
__device__ __forceinline__ void cp16(void* smem, const void* gmem) {
    uint32_t s = (uint32_t)__cvta_generic_to_shared(smem);
    asm volatile("cp.async.cg.shared.global [%0], [%1], 16;\n" :: "r"(s), "l"(gmem));
}
__device__ __forceinline__ void cp_commit() {
    asm volatile("cp.async.commit_group;\n" ::: "memory");
}
template <int N>
__device__ __forceinline__ void cp_wait() {
    asm volatile("cp.async.wait_group %0;\n" :: "n"(N) : "memory");
}

// ---------------- routing kernels -------------------------------------------
__global__ void router_kernel(const float* __restrict__ x,
                              const float* __restrict__ gw) {
    int n = blockIdx.x;
    const float* xr = x + (size_t)n * DMODEL;
    float acc[NEXP];
#pragma unroll
    for (int e = 0; e < NEXP; e++) acc[e] = 0.f;
    for (int d = threadIdx.x; d < DMODEL; d += 256) {
        float xv = xr[d];
#pragma unroll
        for (int e = 0; e < NEXP; e++)
            acc[e] = fmaf(xv, gw[e * DMODEL + d], acc[e]);
    }
#pragma unroll
    for (int e = 0; e < NEXP; e++)
#pragma unroll
        for (int off = 16; off; off >>= 1)
            acc[e] += __shfl_xor_sync(0xffffffffu, acc[e], off);

    __shared__ float red[NEXP][8];
    int w = threadIdx.x >> 5, lane = threadIdx.x & 31;
    if (lane == 0) {
#pragma unroll
        for (int e = 0; e < NEXP; e++) red[e][w] = acc[e];
    }
    __syncthreads();
    if (threadIdx.x < NEXP) {
        float s = 0.f;
#pragma unroll
        for (int ww = 0; ww < 8; ww++) s += red[threadIdx.x][ww];
        g_logits[n * NEXP + threadIdx.x] = s;
    }
}

__global__ void sum_kernel() {
    int e = blockIdx.x;
    float s = 0.f;
    for (int n = threadIdx.x; n < NTOK; n += blockDim.x)
        s += g_logits[n * NEXP + e];
    __shared__ float sm[256];
    sm[threadIdx.x] = s;
    __syncthreads();
    for (int off = 128; off; off >>= 1) {
        if (threadIdx.x < off) sm[threadIdx.x] += sm[threadIdx.x + off];
        __syncthreads();
    }
    if (threadIdx.x == 0) g_sums[e] = sm[0];
}

__global__ void topk_kernel() {
    if (threadIdx.x == 0) {
        int b = 0;
        for (int i = 1; i < NEXP; i++)
            if (g_sums[i] > g_sums[b]) b = i;     // strict > : lower idx on tie
        int s = (b == 0) ? 1 : 0;
        for (int i = 0; i < NEXP; i++)
            if (i != b && g_sums[i] > g_sums[s]) s = i;
        g_sel[0] = b;
        g_sel[1] = s;
    }
}

__global__ void rw_kernel() {
    int n = blockIdx.x * blockDim.x + threadIdx.x;
    if (n >= NTOK) return;
    int s0 = g_sel[0], s1 = g_sel[1];
    float l0 = g_logits[n * NEXP + s0];
    float l1 = g_logits[n * NEXP + s1];
    float m  = fmaxf(l0, l1);
    float e0 = expf(l0 - m), e1 = expf(l1 - m);
    float inv = 1.0f / (e0 + e1);
    g_rw[n * TOPK + 0] = e0 * inv;
    g_rw[n * TOPK + 1] = e1 * inv;
}

// fp32 -> fp16 straight convert (x)
__global__ void cvt_x_h(const float4* __restrict__ src,
                        __half2* __restrict__ dst, size_t n4) {
    for (size_t i = (size_t)blockIdx.x * blockDim.x + threadIdx.x; i < n4;
         i += (size_t)gridDim.x * blockDim.x) {
        float4 v = src[i];
        dst[i * 2 + 0] = __floats2half2_rn(v.x, v.y);
        dst[i * 2 + 1] = __floats2half2_rn(v.z, v.w);
    }
}

// Transpose + fp16-convert selected expert weight: in [K,N] fp32 -> out [N,K] fp16
__global__ void transpose_cvt_h(const float* __restrict__ Wall,
                                __half* __restrict__ out,
                                int kidx, int K, int N) {
    __shared__ float t[32][33];
    int e = g_sel[kidx];
    const float* src = Wall + (size_t)e * K * N;
    int n0 = blockIdx.x * 32, k0 = blockIdx.y * 32;
#pragma unroll
    for (int i = threadIdx.y; i < 32; i += 8)
        t[i][threadIdx.x] = src[(size_t)(k0 + i) * N + n0 + threadIdx.x];
    __syncthreads();
#pragma unroll
    for (int i = threadIdx.y; i < 32; i += 8)
        out[(size_t)(n0 + i) * K + k0 + threadIdx.x] = __float2half_rn(t[threadIdx.x][i]);
}

// ---------------- fp16 GEMM: 128x256 CTA, 64x64 warp, cp.async 4-stage -------
// Both A [M,K] and B^T [N,K] are K-major fp16 -> all fragment loads are half2.
#define BM 128
#define BN 256
#define BK 32
#define ASTRH 40    // halves per A row (BK+8): 80B row stride, conflict-free
#define BSTRH 40    // halves per B row
#define NSTAGE 4
#define A_TILE_H (BM * ASTRH)              // halves
#define B_TILE_H (BN * BSTRH)
#define STAGE_H  (A_TILE_H + B_TILE_H)
#define SMEM_BYTES (NSTAGE * STAGE_H * 2)

__device__ __forceinline__ void mma_f16(float* c, const uint32_t* a, const uint32_t* b) {
    asm volatile(
        "mma.sync.aligned.m16n8k16.row.col.f32.f16.f16.f32 "
        "{%0,%1,%2,%3}, {%4,%5,%6,%7}, {%8,%9}, {%0,%1,%2,%3};\n"
        : "+f"(c[0]), "+f"(c[1]), "+f"(c[2]), "+f"(c[3])
        : "r"(a[0]), "r"(a[1]), "r"(a[2]), "r"(a[3]), "r"(b[0]), "r"(b[1]));
}

__device__ __forceinline__ float gelu_tanh(float x) {
    float x3 = x * x * x;
    float t  = tanhf(0.7978845608028654f * (x + 0.044715f * x3));
    return 0.5f * x * (1.0f + t);
}

// MODE 0: Ch = fp16(gelu(A@B^T + bias))      (h production, C is __half*)
// MODE 1: Cf = rw[:,kidx] * (A@B^T + bias)   (C is float*)
// MODE 2: Cf += rw[:,kidx] * (A@B^T + bias)
template <int MODE>
__global__ void __launch_bounds__(256, 1)
moe_gemm_h(const __half* __restrict__ A,      // [M,K] fp16
           const __half* __restrict__ Bt,     // [N,K] fp16
           const float* __restrict__ Ball,    // bias table [E,N] fp32
           int kidx, int N, int K,
           void* __restrict__ Cv) {
    extern __shared__ __half smh[];
    __half* As = smh;                          // NSTAGE * A_TILE_H
    __half* Bs = smh + NSTAGE * A_TILE_H;      // NSTAGE * B_TILE_H

    const int tid  = threadIdx.x;
    const int lane = tid & 31;
    const int wid  = tid >> 5;
    const int g    = lane >> 2;     // 0..7
    const int tg   = lane & 3;      // 0..3
    const int wm   = wid & 1;       // 64 rows each
    const int wn   = wid >> 1;      // 64 cols each
    const int m0   = blockIdx.y * BM;
    const int n0   = blockIdx.x * BN;

    const int e = g_sel[kidx];
    const float* bias = Ball + (size_t)e * N;

    float acc[4][8][4];
#pragma unroll
    for (int i = 0; i < 4; i++)
#pragma unroll
        for (int j = 0; j < 8; j++)
#pragma unroll
            for (int r = 0; r < 4; r++) acc[i][j][r] = 0.f;

    const int KT = K / BK;

    auto issue_stage = [&](int s, int kt) {
        const int k0 = kt * BK;
        __half* as = As + s * A_TILE_H;
        __half* bs = Bs + s * B_TILE_H;
        // A: 128 rows x 64B = 512 16B-chunks (2/thread)
#pragma unroll
        for (int i = 0; i < 2; i++) {
            int idx = tid + i * 256;
            int r = idx >> 2, ch = idx & 3;
            cp16(&as[r * ASTRH + ch * 8], A + (size_t)(m0 + r) * K + k0 + ch * 8);
        }
        // B: 256 rows x 64B = 1024 chunks (4/thread)
#pragma unroll
        for (int i = 0; i < 4; i++) {
            int idx = tid + i * 256;
            int r = idx >> 2, ch = idx & 3;
            cp16(&bs[r * BSTRH + ch * 8], Bt + (size_t)(n0 + r) * K + k0 + ch * 8);
        }
    };

    // prologue: stages 0..2
    issue_stage(0, 0); cp_commit();
    if (KT > 1) issue_stage(1, 1);
    cp_commit();
    if (KT > 2) issue_stage(2, 2);
    cp_commit();

    for (int kt = 0; kt < KT; kt++) {
        cp_wait<2>();
        __syncthreads();

        if (kt + 3 < KT) issue_stage((kt + 3) & (NSTAGE - 1), kt + 3);
        cp_commit();

        const __half* as = As + (kt & (NSTAGE - 1)) * A_TILE_H;
        const __half* bs = Bs + (kt & (NSTAGE - 1)) * B_TILE_H;

#pragma unroll
        for (int ks = 0; ks < 2; ks++) {
            const int kk = ks * 16;
            uint32_t af[4][4], bf[8][2];
#pragma unroll
            for (int mt = 0; mt < 4; mt++) {
                int row = wm * 64 + mt * 16;
                af[mt][0] = *(const uint32_t*)&as[(row + g)     * ASTRH + kk + tg * 2];
                af[mt][1] = *(const uint32_t*)&as[(row + g + 8) * ASTRH + kk + tg * 2];
                af[mt][2] = *(const uint32_t*)&as[(row + g)     * ASTRH + kk + tg * 2 + 8];
                af[mt][3] = *(const uint32_t*)&as[(row + g + 8) * ASTRH + kk + tg * 2 + 8];
            }
#pragma unroll
            for (int nt = 0; nt < 8; nt++) {
                int col = wn * 64 + nt * 8;
                bf[nt][0] = *(const uint32_t*)&bs[(col + g) * BSTRH + kk + tg * 2];
                bf[nt][1] = *(const uint32_t*)&bs[(col + g) * BSTRH + kk + tg * 2 + 8];
            }
#pragma unroll
            for (int mt = 0; mt < 4; mt++)
#pragma unroll
                for (int nt = 0; nt < 8; nt++)
                    mma_f16(acc[mt][nt], af[mt], bf[nt]);
        }
        // next iteration's __syncthreads() protects the stage being overwritten
    }

    // ---------------- epilogue ----------------
#pragma unroll
    for (int mt = 0; mt < 4; mt++) {
        int r0 = m0 + wm * 64 + mt * 16 + g;
        float w0 = 0.f, w1 = 0.f;
        if (MODE != 0) {
            w0 = g_rw[(size_t)r0 * TOPK + kidx];
            w1 = g_rw[(size_t)(r0 + 8) * TOPK + kidx];
        }
#pragma unroll
        for (int nt = 0; nt < 8; nt++) {
            int cc = n0 + wn * 64 + nt * 8 + tg * 2;
            const float* cr = acc[mt][nt];
            float b0 = bias[cc], b1v = bias[cc + 1];
            float y00 = cr[0] + b0, y01 = cr[1] + b1v;
            float y10 = cr[2] + b0, y11 = cr[3] + b1v;
            if (MODE == 0) {
                __half* C = (__half*)Cv;
                __half2* p0 = (__half2*)(C + (size_t)r0 * N + cc);
                __half2* p1 = (__half2*)(C + (size_t)(r0 + 8) * N + cc);
                *p0 = __floats2half2_rn(gelu_tanh(y00), gelu_tanh(y01));
                *p1 = __floats2half2_rn(gelu_tanh(y10), gelu_tanh(y11));
            } else {
                float* C = (float*)Cv;
                float* p0 = C + (size_t)r0 * N + cc;
                float* p1 = C + (size_t)(r0 + 8) * N + cc;
                if (MODE == 1) {
                    float2 o0 = {w0 * y00, w0 * y01};
                    float2 o1 = {w1 * y10, w1 * y11};
                    *reinterpret_cast<float2*>(p0) = o0;
                    *reinterpret_cast<float2*>(p1) = o1;
                } else {
                    float2 c0 = *reinterpret_cast<float2*>(p0);
                    float2 c1 = *reinterpret_cast<float2*>(p1);
                    c0.x += w0 * y00; c0.y += w0 * y01;
                    c1.x += w1 * y10; c1.y += w1 * y11;
                    *reinterpret_cast<float2*>(p0) = c0;
                    *reinterpret_cast<float2*>(p1) = c1;
                }
            }
        }
    }
}

// ---------------- launch -----------------------------------------------------
extern "C" void kernel_launch(void* const* d_in, const int* in_sizes, int n_in,
                              void* d_out, int out_size) {
    const float* x  = (const float*)d_in[0];   // [8192,2048]
    const float* gw = (const float*)d_in[1];   // [8,2048]
    const float* w1 = (const float*)d_in[2];   // [8,2048,8192]
    const float* b1 = (const float*)d_in[3];   // [8,8192]
    const float* w2 = (const float*)d_in[4];   // [8,8192,2048]
    const float* b2 = (const float*)d_in[5];   // [8,2048]
    float* out = (float*)d_out;                // [8192,2048]

    __half *xh, *hh, *w1t0, *w2t0;
    cudaGetSymbolAddress((void**)&xh,   g_xh);
    cudaGetSymbolAddress((void**)&hh,   g_hh);
    cudaGetSymbolAddress((void**)&w1t0, g_w1t);
    cudaGetSymbolAddress((void**)&w2t0, g_w2t);
    __half* w1t1 = w1t0 + (size_t)FFDIM * DMODEL;
    __half* w2t1 = w2t0 + (size_t)DMODEL * FFDIM;

    cudaFuncSetAttribute(moe_gemm_h<0>, cudaFuncAttributeMaxDynamicSharedMemorySize, SMEM_BYTES);
    cudaFuncSetAttribute(moe_gemm_h<1>, cudaFuncAttributeMaxDynamicSharedMemorySize, SMEM_BYTES);
    cudaFuncSetAttribute(moe_gemm_h<2>, cudaFuncAttributeMaxDynamicSharedMemorySize, SMEM_BYTES);

    router_kernel<<<NTOK, 256>>>(x, gw);
    sum_kernel<<<NEXP, 256>>>();
    topk_kernel<<<1, 32>>>();
    rw_kernel<<<NTOK / 256, 256>>>();

    // operand pre-passes: x -> fp16; selected weights -> transposed fp16 [N,K]
    cvt_x_h<<<2048, 256>>>((const float4*)x, (__half2*)xh, ((size_t)NTOK * DMODEL) >> 2);
    dim3 tb(32, 8);
    dim3 tg1(FFDIM / 32, DMODEL / 32);   // w1: K=2048, N=8192
    dim3 tg2(DMODEL / 32, FFDIM / 32);   // w2: K=8192, N=2048
    transpose_cvt_h<<<tg1, tb>>>(w1, w1t0, 0, DMODEL, FFDIM);
    transpose_cvt_h<<<tg1, tb>>>(w1, w1t1, 1, DMODEL, FFDIM);
    transpose_cvt_h<<<tg2, tb>>>(w2, w2t0, 0, FFDIM, DMODEL);
    transpose_cvt_h<<<tg2, tb>>>(w2, w2t1, 1, FFDIM, DMODEL);

    dim3 blk(256);
    dim3 g1(FFDIM / BN, NTOK / BM);   // (32,64)
    dim3 g2(DMODEL / BN, NTOK / BM);  // (8,64)

    moe_gemm_h<0><<<g1, blk, SMEM_BYTES>>>(xh, w1t0, b1, 0, FFDIM,  DMODEL, hh);
    moe_gemm_h<1><<<g2, blk, SMEM_BYTES>>>(hh, w2t0, b2, 0, DMODEL, FFDIM,  out);
    moe_gemm_h<0><<<g1, blk, SMEM_BYTES>>>(xh, w1t1, b1, 1, FFDIM,  DMODEL, hh);
    moe_gemm_h<2><<<g2, blk, SMEM_BYTES>>>(hh, w2t1, b2, 1, DMODEL, FFDIM,  out);
}

// round 10
// speedup vs baseline: 2.2284x; 1.0183x over previous
#include <cuda_runtime.h>
#include <cuda_fp16.h>
#include <cstdint>

// Problem constants (B=2, S=4096, D=2048, E=8, DFF=8192, TOP_K=2)
#define NTOK   8192
#define DMODEL 2048
#define NEXP   8
#define FFDIM  8192
#define TOPK   2

// ---------------- device scratch (allocation-free rule: __device__ globals) --
__device__ float  g_logits[NTOK * NEXP];
__device__ float  g_sums[NEXP];
__device__ int    g_sel[TOPK];
__device__ float  g_rw[NTOK * TOPK];
__device__ __half g_xh[(size_t)NTOK * DMODEL];        // x  fp16 [M,K]
__device__ __half g_hh[(size_t)NTOK * FFDIM];         // h  fp16 [M,K]
__device__ __half g_w1t[2][(size_t)FFDIM * DMODEL];   // w1^T fp16 [N=FF, K=D]
__device__ __half g_w2t[2][(size_t)DMODEL * FFDIM];   // w2^T fp16 [N=D,  K=FF]

// ---------------- helpers ----------------------------------------------------
__device__ __forceinline__ void cp16(void* smem, const void* gmem) {
    uint32_t s = (uint32_t)__cvta_generic_to_shared(smem);
    asm volatile("cp.async.cg.shared.global [%0], [%1], 16;\n" :: "r"(s), "l"(gmem));
}
__device__ __forceinline__ void cp_commit() {
    asm volatile("cp.async.commit_group;\n" ::: "memory");
}
template <int N>
__device__ __forceinline__ void cp_wait() {
    asm volatile("cp.async.wait_group %0;\n" :: "n"(N) : "memory");
}
__device__ __forceinline__ void ldsm4(uint32_t* r, uint32_t addr) {
    asm volatile("ldmatrix.sync.aligned.m8n8.x4.shared.b16 {%0,%1,%2,%3}, [%4];"
                 : "=r"(r[0]), "=r"(r[1]), "=r"(r[2]), "=r"(r[3]) : "r"(addr));
}

// ---------------- routing kernels -------------------------------------------
__global__ void router_kernel(const float* __restrict__ x,
                              const float* __restrict__ gw) {
    int n = blockIdx.x;
    const float* xr = x + (size_t)n * DMODEL;
    float acc[NEXP];
#pragma unroll
    for (int e = 0; e < NEXP; e++) acc[e] = 0.f;
    for (int d = threadIdx.x; d < DMODEL; d += 256) {
        float xv = xr[d];
#pragma unroll
        for (int e = 0; e < NEXP; e++)
            acc[e] = fmaf(xv, gw[e * DMODEL + d], acc[e]);
    }
#pragma unroll
    for (int e = 0; e < NEXP; e++)
#pragma unroll
        for (int off = 16; off; off >>= 1)
            acc[e] += __shfl_xor_sync(0xffffffffu, acc[e], off);

    __shared__ float red[NEXP][8];
    int w = threadIdx.x >> 5, lane = threadIdx.x & 31;
    if (lane == 0) {
#pragma unroll
        for (int e = 0; e < NEXP; e++) red[e][w] = acc[e];
    }
    __syncthreads();
    if (threadIdx.x < NEXP) {
        float s = 0.f;
#pragma unroll
        for (int ww = 0; ww < 8; ww++) s += red[threadIdx.x][ww];
        g_logits[n * NEXP + threadIdx.x] = s;
    }
}

__global__ void sum_kernel() {
    int e = blockIdx.x;
    float s = 0.f;
    for (int n = threadIdx.x; n < NTOK; n += blockDim.x)
        s += g_logits[n * NEXP + e];
    __shared__ float sm[256];
    sm[threadIdx.x] = s;
    __syncthreads();
    for (int off = 128; off; off >>= 1) {
        if (threadIdx.x < off) sm[threadIdx.x] += sm[threadIdx.x + off];
        __syncthreads();
    }
    if (threadIdx.x == 0) g_sums[e] = sm[0];
}

__global__ void topk_kernel() {
    if (threadIdx.x == 0) {
        int b = 0;
        for (int i = 1; i < NEXP; i++)
            if (g_sums[i] > g_sums[b]) b = i;     // strict > : lower idx on tie
        int s = (b == 0) ? 1 : 0;
        for (int i = 0; i < NEXP; i++)
            if (i != b && g_sums[i] > g_sums[s]) s = i;
        g_sel[0] = b;
        g_sel[1] = s;
    }
}

__global__ void rw_kernel() {
    int n = blockIdx.x * blockDim.x + threadIdx.x;
    if (n >= NTOK) return;
    int s0 = g_sel[0], s1 = g_sel[1];
    float l0 = g_logits[n * NEXP + s0];
    float l1 = g_logits[n * NEXP + s1];
    float m  = fmaxf(l0, l1);
    float e0 = expf(l0 - m), e1 = expf(l1 - m);
    float inv = 1.0f / (e0 + e1);
    g_rw[n * TOPK + 0] = e0 * inv;
    g_rw[n * TOPK + 1] = e1 * inv;
}

// fp32 -> fp16 straight convert (x)
__global__ void cvt_x_h(const float4* __restrict__ src,
                        __half2* __restrict__ dst, size_t n4) {
    for (size_t i = (size_t)blockIdx.x * blockDim.x + threadIdx.x; i < n4;
         i += (size_t)gridDim.x * blockDim.x) {
        float4 v = src[i];
        dst[i * 2 + 0] = __floats2half2_rn(v.x, v.y);
        dst[i * 2 + 1] = __floats2half2_rn(v.z, v.w);
    }
}

// Transpose + fp16-convert selected expert weight: in [K,N] fp32 -> out [N,K] fp16
__global__ void transpose_cvt_h(const float* __restrict__ Wall,
                                __half* __restrict__ out,
                                int kidx, int K, int N) {
    __shared__ float t[32][33];
    int e = g_sel[kidx];
    const float* src = Wall + (size_t)e * K * N;
    int n0 = blockIdx.x * 32, k0 = blockIdx.y * 32;
#pragma unroll
    for (int i = threadIdx.y; i < 32; i += 8)
        t[i][threadIdx.x] = src[(size_t)(k0 + i) * N + n0 + threadIdx.x];
    __syncthreads();
#pragma unroll
    for (int i = threadIdx.y; i < 32; i += 8)
        out[(size_t)(n0 + i) * K + k0 + threadIdx.x] = __float2half_rn(t[threadIdx.x][i]);
}

// ---------------- fp16 GEMM: 128x256 CTA, 64x64 warp, ldmatrix + cp.async ----
#define BM 128
#define BN 256
#define BK 32
#define ASTRH 40    // halves per A row (BK+8): 80B stride; 16B-aligned, ldsm conflict-free
#define BSTRH 40
#define NSTAGE 4
#define A_TILE_H (BM * ASTRH)              // halves
#define B_TILE_H (BN * BSTRH)
#define SMEM_BYTES (NSTAGE * (A_TILE_H + B_TILE_H) * 2)

__device__ __forceinline__ void mma_f16(float* c, const uint32_t* a, const uint32_t* b) {
    asm volatile(
        "mma.sync.aligned.m16n8k16.row.col.f32.f16.f16.f32 "
        "{%0,%1,%2,%3}, {%4,%5,%6,%7}, {%8,%9}, {%0,%1,%2,%3};\n"
        : "+f"(c[0]), "+f"(c[1]), "+f"(c[2]), "+f"(c[3])
        : "r"(a[0]), "r"(a[1]), "r"(a[2]), "r"(a[3]), "r"(b[0]), "r"(b[1]));
}

__device__ __forceinline__ float gelu_tanh(float x) {
    float x3 = x * x * x;
    float t  = tanhf(0.7978845608028654f * (x + 0.044715f * x3));
    return 0.5f * x * (1.0f + t);
}

// MODE 0: Ch = fp16(gelu(A@B^T + bias))      (h production, C is __half*)
// MODE 1: Cf = rw[:,kidx] * (A@B^T + bias)   (C is float*)
// MODE 2: Cf += rw[:,kidx] * (A@B^T + bias)
template <int MODE>
__global__ void __launch_bounds__(256, 1)
moe_gemm_h(const __half* __restrict__ A,      // [M,K] fp16
           const __half* __restrict__ Bt,     // [N,K] fp16
           const float* __restrict__ Ball,    // bias table [E,N] fp32
           int kidx, int N, int K,
           void* __restrict__ Cv) {
    extern __shared__ __half smh[];
    __half* As = smh;                          // NSTAGE * A_TILE_H
    __half* Bs = smh + NSTAGE * A_TILE_H;      // NSTAGE * B_TILE_H

    const int tid  = threadIdx.x;
    const int lane = tid & 31;
    const int wid  = tid >> 5;
    const int g    = lane >> 2;     // 0..7
    const int tg   = lane & 3;      // 0..3
    const int wm   = wid & 1;       // 64 rows each
    const int wn   = wid >> 1;      // 64 cols each
    const int m0   = blockIdx.y * BM;
    const int n0   = blockIdx.x * BN;

    const int e = g_sel[kidx];
    const float* bias = Ball + (size_t)e * N;

    // ldmatrix per-lane base byte-offsets (kk = 0)
    const int lr  = lane & 7;
    const int sel = lane >> 3;      // 0..3
    uint32_t aoff[4], boff[4];
#pragma unroll
    for (int mt = 0; mt < 4; mt++) {
        int row = wm * 64 + mt * 16 + (sel & 1) * 8 + lr;
        aoff[mt] = (uint32_t)(row * ASTRH + (sel >> 1) * 8) * 2;
    }
#pragma unroll
    for (int p = 0; p < 4; p++) {
        int nn = wn * 64 + p * 16 + (sel >> 1) * 8 + lr;
        boff[p] = (uint32_t)(nn * BSTRH + (sel & 1) * 8) * 2;
    }
    const uint32_t As_u = (uint32_t)__cvta_generic_to_shared(As);
    const uint32_t Bs_u = (uint32_t)__cvta_generic_to_shared(Bs);

    float acc[4][8][4];
#pragma unroll
    for (int i = 0; i < 4; i++)
#pragma unroll
        for (int j = 0; j < 8; j++)
#pragma unroll
            for (int r = 0; r < 4; r++) acc[i][j][r] = 0.f;

    const int KT = K / BK;

    auto issue_stage = [&](int s, int kt) {
        const int k0 = kt * BK;
        __half* as = As + s * A_TILE_H;
        __half* bs = Bs + s * B_TILE_H;
#pragma unroll
        for (int i = 0; i < 2; i++) {              // A: 512 chunks
            int idx = tid + i * 256;
            int r = idx >> 2, ch = idx & 3;
            cp16(&as[r * ASTRH + ch * 8], A + (size_t)(m0 + r) * K + k0 + ch * 8);
        }
#pragma unroll
        for (int i = 0; i < 4; i++) {              // B: 1024 chunks
            int idx = tid + i * 256;
            int r = idx >> 2, ch = idx & 3;
            cp16(&bs[r * BSTRH + ch * 8], Bt + (size_t)(n0 + r) * K + k0 + ch * 8);
        }
    };

    // prologue: stages 0..2
    issue_stage(0, 0); cp_commit();
    if (KT > 1) issue_stage(1, 1);
    cp_commit();
    if (KT > 2) issue_stage(2, 2);
    cp_commit();

    for (int kt = 0; kt < KT; kt++) {
        cp_wait<2>();
        __syncthreads();

        if (kt + 3 < KT) issue_stage((kt + 3) & (NSTAGE - 1), kt + 3);
        cp_commit();

        const uint32_t a_base = As_u + (uint32_t)((kt & (NSTAGE - 1)) * A_TILE_H) * 2;
        const uint32_t b_base = Bs_u + (uint32_t)((kt & (NSTAGE - 1)) * B_TILE_H) * 2;

#pragma unroll
        for (int ks = 0; ks < 2; ks++) {
            const uint32_t ko = ks * 32;          // +16 halves
            uint32_t af[4][4], bq[4][4];
#pragma unroll
            for (int mt = 0; mt < 4; mt++) ldsm4(af[mt], a_base + aoff[mt] + ko);
#pragma unroll
            for (int p = 0; p < 4; p++)  ldsm4(bq[p],  b_base + boff[p] + ko);
#pragma unroll
            for (int mt = 0; mt < 4; mt++)
#pragma unroll
                for (int nt = 0; nt < 8; nt++)
                    mma_f16(acc[mt][nt], af[mt], &bq[nt >> 1][(nt & 1) * 2]);
        }
        // next iteration's __syncthreads() protects the stage being overwritten
    }

    // ---------------- epilogue ----------------
#pragma unroll
    for (int mt = 0; mt < 4; mt++) {
        int r0 = m0 + wm * 64 + mt * 16 + g;
        float w0 = 0.f, w1 = 0.f;
        if (MODE != 0) {
            w0 = g_rw[(size_t)r0 * TOPK + kidx];
            w1 = g_rw[(size_t)(r0 + 8) * TOPK + kidx];
        }
#pragma unroll
        for (int nt = 0; nt < 8; nt++) {
            int cc = n0 + wn * 64 + nt * 8 + tg * 2;
            const float* cr = acc[mt][nt];
            float b0 = bias[cc], b1v = bias[cc + 1];
            float y00 = cr[0] + b0, y01 = cr[1] + b1v;
            float y10 = cr[2] + b0, y11 = cr[3] + b1v;
            if (MODE == 0) {
                __half* C = (__half*)Cv;
                __half2* p0 = (__half2*)(C + (size_t)r0 * N + cc);
                __half2* p1 = (__half2*)(C + (size_t)(r0 + 8) * N + cc);
                *p0 = __floats2half2_rn(gelu_tanh(y00), gelu_tanh(y01));
                *p1 = __floats2half2_rn(gelu_tanh(y10), gelu_tanh(y11));
            } else {
                float* C = (float*)Cv;
                float* p0 = C + (size_t)r0 * N + cc;
                float* p1 = C + (size_t)(r0 + 8) * N + cc;
                if (MODE == 1) {
                    float2 o0 = {w0 * y00, w0 * y01};
                    float2 o1 = {w1 * y10, w1 * y11};
                    *reinterpret_cast<float2*>(p0) = o0;
                    *reinterpret_cast<float2*>(p1) = o1;
                } else {
                    float2 c0 = *reinterpret_cast<float2*>(p0);
                    float2 c1 = *reinterpret_cast<float2*>(p1);
                    c0.x += w0 * y00; c0.y += w0 * y01;
                    c1.x += w1 * y10; c1.y += w1 * y11;
                    *reinterpret_cast<float2*>(p0) = c0;
                    *reinterpret_cast<float2*>(p1) = c1;
                }
            }
        }
    }
}

// ---------------- launch -----------------------------------------------------
extern "C" void kernel_launch(void* const* d_in, const int* in_sizes, int n_in,
                              void* d_out, int out_size) {
    const float* x  = (const float*)d_in[0];   // [8192,2048]
    const float* gw = (const float*)d_in[1];   // [8,2048]
    const float* w1 = (const float*)d_in[2];   // [8,2048,8192]
    const float* b1 = (const float*)d_in[3];   // [8,8192]
    const float* w2 = (const float*)d_in[4];   // [8,8192,2048]
    const float* b2 = (const float*)d_in[5];   // [8,2048]
    float* out = (float*)d_out;                // [8192,2048]

    __half *xh, *hh, *w1t0, *w2t0;
    cudaGetSymbolAddress((void**)&xh,   g_xh);
    cudaGetSymbolAddress((void**)&hh,   g_hh);
    cudaGetSymbolAddress((void**)&w1t0, g_w1t);
    cudaGetSymbolAddress((void**)&w2t0, g_w2t);
    __half* w1t1 = w1t0 + (size_t)FFDIM * DMODEL;
    __half* w2t1 = w2t0 + (size_t)DMODEL * FFDIM;

    cudaFuncSetAttribute(moe_gemm_h<0>, cudaFuncAttributeMaxDynamicSharedMemorySize, SMEM_BYTES);
    cudaFuncSetAttribute(moe_gemm_h<1>, cudaFuncAttributeMaxDynamicSharedMemorySize, SMEM_BYTES);
    cudaFuncSetAttribute(moe_gemm_h<2>, cudaFuncAttributeMaxDynamicSharedMemorySize, SMEM_BYTES);

    router_kernel<<<NTOK, 256>>>(x, gw);
    sum_kernel<<<NEXP, 256>>>();
    topk_kernel<<<1, 32>>>();
    rw_kernel<<<NTOK / 256, 256>>>();

    // operand pre-passes: x -> fp16; selected weights -> transposed fp16 [N,K]
    cvt_x_h<<<2048, 256>>>((const float4*)x, (__half2*)xh, ((size_t)NTOK * DMODEL) >> 2);
    dim3 tb(32, 8);
    dim3 tg1(FFDIM / 32, DMODEL / 32);   // w1: K=2048, N=8192
    dim3 tg2(DMODEL / 32, FFDIM / 32);   // w2: K=8192, N=2048
    transpose_cvt_h<<<tg1, tb>>>(w1, w1t0, 0, DMODEL, FFDIM);
    transpose_cvt_h<<<tg1, tb>>>(w1, w1t1, 1, DMODEL, FFDIM);
    transpose_cvt_h<<<tg2, tb>>>(w2, w2t0, 0, FFDIM, DMODEL);
    transpose_cvt_h<<<tg2, tb>>>(w2, w2t1, 1, FFDIM, DMODEL);

    dim3 blk(256);
    dim3 g1(FFDIM / BN, NTOK / BM);   // (32,64)
    dim3 g2(DMODEL / BN, NTOK / BM);  // (8,64)

    moe_gemm_h<0><<<g1, blk, SMEM_BYTES>>>(xh, w1t0, b1, 0, FFDIM,  DMODEL, hh);
    moe_gemm_h<1><<<g2, blk, SMEM_BYTES>>>(hh, w2t0, b2, 0, DMODEL, FFDIM,  out);
    moe_gemm_h<0><<<g1, blk, SMEM_BYTES>>>(xh, w1t1, b1, 1, FFDIM,  DMODEL, hh);
    moe_gemm_h<2><<<g2, blk, SMEM_BYTES>>>(hh, w2t1, b2, 1, DMODEL, FFDIM,  out);
}